// round 3
// baseline (speedup 1.0000x reference)
#include <cuda_runtime.h>
#include <math.h>

// ---------------- problem constants ----------------
#define BSZ     2
#define SEQL    4096
#define DMODEL  768
#define DSTATE  128
#define HD      64
#define DIN     1536
#define NH      24
#define DXBC    1792          // DIN + 2*DSTATE
#define DPROJ   3352          // 2*DIN + 2*DSTATE + NH
#define CHUNKQ  128
#define NCH     32            // SEQL / CHUNKQ
#define NROWS   (BSZ*SEQL)    // 8192
#define NBC     (BSZ*NCH)     // 64

// ---------------- scratch (static device memory; no runtime allocs) ----------------
__device__ float g_zx[(size_t)NROWS*DPROJ];            // in_proj output  (110 MB)
__device__ float g_xbc[(size_t)NROWS*DXBC];            // conv+silu out   (59 MB)
__device__ float g_dt[NROWS*NH];                       // softplus dt
__device__ float g_acum[NROWS*NH];                     // per-chunk cumsum of dt*A
__device__ float g_alast[NBC*NH];                      // chunk-final acum
__device__ float g_cb[(size_t)NBC*CHUNKQ*CHUNKQ];      // C@B^T per chunk (4.2 MB)
__device__ float g_states[(size_t)NBC*NH*HD*DSTATE];   // per-chunk states (50 MB)
__device__ float g_prev[(size_t)NBC*NH*HD*DSTATE];     // state entering chunk (50 MB)
__device__ float g_y[(size_t)NROWS*DIN];               // ssd output / normalized y (50 MB)

// ---------------- generic tiled fp32 GEMM: C = A(MxK) * B(NxK)^T ----------------
// EP=1: C = sigmoid(gate1)*C + feat  (final residual epilogue)
template<int EP>
__global__ void gemm_nt(const float* __restrict__ A, const float* __restrict__ B,
                        float* __restrict__ C, int M, int N, int K,
                        const float* __restrict__ feat, const float* __restrict__ gate1)
{
    __shared__ float As[16][64];
    __shared__ float Bs[16][64];
    const int tid  = threadIdx.x;
    const int m0   = blockIdx.y * 64;
    const int n0   = blockIdx.x * 64;
    const int lrow = tid >> 2;          // 0..63
    const int lk   = (tid & 3) * 4;     // 0,4,8,12
    const int ty   = tid >> 4;          // 0..15
    const int tx   = tid & 15;          // 0..15

    float acc[4][4] = {};
    for (int k0 = 0; k0 < K; k0 += 16) {
        float4 av = *(const float4*)(A + (size_t)(m0 + lrow) * K + k0 + lk);
        As[lk+0][lrow] = av.x; As[lk+1][lrow] = av.y;
        As[lk+2][lrow] = av.z; As[lk+3][lrow] = av.w;
        int bn = n0 + lrow;
        float4 bv = make_float4(0.f, 0.f, 0.f, 0.f);
        if (bn < N) bv = *(const float4*)(B + (size_t)bn * K + k0 + lk);
        Bs[lk+0][lrow] = bv.x; Bs[lk+1][lrow] = bv.y;
        Bs[lk+2][lrow] = bv.z; Bs[lk+3][lrow] = bv.w;
        __syncthreads();
        #pragma unroll
        for (int kk = 0; kk < 16; kk++) {
            float4 a = *(const float4*)&As[kk][ty*4];
            float4 b = *(const float4*)&Bs[kk][tx*4];
            acc[0][0] += a.x*b.x; acc[0][1] += a.x*b.y; acc[0][2] += a.x*b.z; acc[0][3] += a.x*b.w;
            acc[1][0] += a.y*b.x; acc[1][1] += a.y*b.y; acc[1][2] += a.y*b.z; acc[1][3] += a.y*b.w;
            acc[2][0] += a.z*b.x; acc[2][1] += a.z*b.y; acc[2][2] += a.z*b.z; acc[2][3] += a.z*b.w;
            acc[3][0] += a.w*b.x; acc[3][1] += a.w*b.y; acc[3][2] += a.w*b.z; acc[3][3] += a.w*b.w;
        }
        __syncthreads();
    }
    float g = 0.f;
    if (EP) g = 1.f / (1.f + expf(-gate1[0]));
    #pragma unroll
    for (int i = 0; i < 4; i++) {
        int m = m0 + ty*4 + i;
        #pragma unroll
        for (int j = 0; j < 4; j++) {
            int n = n0 + tx*4 + j;
            if (n < N) {
                float v = acc[i][j];
                if (EP) v = g * v + feat[(size_t)m * N + n];
                C[(size_t)m * N + n] = v;
            }
        }
    }
}

// ---------------- depthwise causal conv (width 4) + bias + SiLU ----------------
__global__ void conv_silu_kernel(const float* __restrict__ cw, const float* __restrict__ cb)
{
    int idx = blockIdx.x * blockDim.x + threadIdx.x;
    if (idx >= NROWS * DXBC) return;
    int ch  = idx % DXBC;
    int row = idx / DXBC;
    int l   = row % SEQL;
    float acc = cb[ch];
    #pragma unroll
    for (int k = 0; k < 4; k++) {
        int ls = l + k - 3;
        if (ls >= 0)
            acc += cw[ch*4 + k] * g_zx[(size_t)(row + k - 3) * DPROJ + DIN + ch];
    }
    g_xbc[idx] = acc / (1.f + expf(-acc));   // silu
}

// ---------------- dt = softplus(raw + dt_bias) ----------------
__global__ void dt_kernel(const float* __restrict__ dt_bias)
{
    int idx = blockIdx.x * blockDim.x + threadIdx.x;
    if (idx >= NROWS * NH) return;
    int h   = idx % NH;
    int row = idx / NH;
    float v = g_zx[(size_t)row * DPROJ + (DIN + DXBC) + h] + dt_bias[h];
    g_dt[idx] = (v > 20.f) ? v : log1pf(expf(v));
}

// ---------------- per-chunk inclusive cumsum of Adt = dt * (-exp(A_log)) ----------------
__global__ void acum_kernel(const float* __restrict__ A_log)
{
    int h  = blockIdx.x % NH;
    int bc = blockIdx.x / NH;
    int l  = threadIdx.x;   // 128
    __shared__ float s[CHUNKQ];
    float Ah = -expf(A_log[h]);
    int row = bc * CHUNKQ + l;
    s[l] = g_dt[row * NH + h] * Ah;
    __syncthreads();
    for (int off = 1; off < CHUNKQ; off <<= 1) {
        float v = (l >= off) ? s[l - off] : 0.f;
        __syncthreads();
        s[l] += v;
        __syncthreads();
    }
    g_acum[row * NH + h] = s[l];
    if (l == CHUNKQ - 1) g_alast[bc * NH + h] = s[l];
}

// ---------------- CB[l,s] = sum_n C[l,n]*B[s,n] per chunk ----------------
#define CB_SMEM_BYTES ((CHUNKQ*CHUNKQ + CHUNKQ*132) * 4)
__global__ void cb_kernel()
{
    extern __shared__ float sm[];
    float* Cs  = sm;                    // [128][128]  l-major
    float* BsT = sm + CHUNKQ*CHUNKQ;    // [128][132]  n-major (transposed, padded)
    int bc  = blockIdx.x;
    int tid = threadIdx.x;              // 256
    int row0 = bc * CHUNKQ;
    for (int i = tid; i < CHUNKQ*CHUNKQ; i += 256) {
        int l = i >> 7, n = i & 127;
        const float* base = &g_xbc[(size_t)(row0 + l) * DXBC];
        Cs[i]            = base[DIN + DSTATE + n];
        BsT[n*132 + l]   = base[DIN + n];
    }
    __syncthreads();
    int l  = tid >> 1;
    int s0 = (tid & 1) * 64;
    float acc[64] = {};
    for (int n = 0; n < 128; n++) {
        float cv = Cs[l*128 + n];
        const float4* bp = (const float4*)&BsT[n*132 + s0];
        #pragma unroll
        for (int j4 = 0; j4 < 16; j4++) {
            float4 b = bp[j4];
            acc[4*j4+0] += cv*b.x; acc[4*j4+1] += cv*b.y;
            acc[4*j4+2] += cv*b.z; acc[4*j4+3] += cv*b.w;
        }
    }
    float* outp = &g_cb[(size_t)bc*CHUNKQ*CHUNKQ + l*CHUNKQ + s0];
    #pragma unroll
    for (int j4 = 0; j4 < 16; j4++)
        ((float4*)outp)[j4] = make_float4(acc[4*j4], acc[4*j4+1], acc[4*j4+2], acc[4*j4+3]);
}

// ---------------- states[p,n] = sum_l dt[l]*exp(Alast-Acum[l]) * x[l,p] * B[l,n] ----------------
#define ST_SMEM_BYTES ((128 + 8192 + 16384) * 4)
__global__ void states_kernel()
{
    extern __shared__ float sm[];
    float* wfac = sm;            // [128]
    float* xw   = sm + 128;      // [128][64]
    float* Bsm  = xw + 8192;     // [128][128]
    int h  = blockIdx.x % NH;
    int bc = blockIdx.x / NH;
    int tid = threadIdx.x;       // 256
    int row0 = bc * CHUNKQ;
    float alast = g_alast[bc*NH + h];
    if (tid < 128)
        wfac[tid] = g_dt[(row0+tid)*NH + h] * expf(alast - g_acum[(row0+tid)*NH + h]);
    __syncthreads();
    for (int i = tid; i < 8192; i += 256) {
        int l = i >> 6, p = i & 63;
        xw[i] = g_xbc[(size_t)(row0+l)*DXBC + h*HD + p] * wfac[l];
    }
    for (int i = tid; i < 16384; i += 256) {
        int l = i >> 7, n = i & 127;
        Bsm[i] = g_xbc[(size_t)(row0+l)*DXBC + DIN + n];
    }
    __syncthreads();
    int tp = tid >> 4, tn = tid & 15;
    int p0 = tp*4, n0 = tn*8;
    float acc[4][8] = {};
    for (int l = 0; l < 128; l++) {
        float4 a  = *(const float4*)&xw[l*64 + p0];
        float4 b0 = *(const float4*)&Bsm[l*128 + n0];
        float4 b1 = *(const float4*)&Bsm[l*128 + n0 + 4];
        float av[4] = {a.x, a.y, a.z, a.w};
        float bv[8] = {b0.x, b0.y, b0.z, b0.w, b1.x, b1.y, b1.z, b1.w};
        #pragma unroll
        for (int i = 0; i < 4; i++)
            #pragma unroll
            for (int j = 0; j < 8; j++)
                acc[i][j] += av[i] * bv[j];
    }
    float* outb = &g_states[((size_t)(bc*NH) + h) * HD * DSTATE];
    #pragma unroll
    for (int i = 0; i < 4; i++) {
        *(float4*)&outb[(p0+i)*DSTATE + n0]     = make_float4(acc[i][0], acc[i][1], acc[i][2], acc[i][3]);
        *(float4*)&outb[(p0+i)*DSTATE + n0 + 4] = make_float4(acc[i][4], acc[i][5], acc[i][6], acc[i][7]);
    }
}

// ---------------- inter-chunk state recurrence: prev[c] = prev[c-1]*exp(Alast[c-1]) + states[c-1] ----------------
__global__ void scan_kernel()
{
    int h = blockIdx.x % NH;
    int b = blockIdx.x / NH;
    int tid = threadIdx.x;   // 512
    float S[16];
    #pragma unroll
    for (int i = 0; i < 16; i++) S[i] = 0.f;
    for (int c = 0; c < NCH; c++) {
        int bc = b*NCH + c;
        size_t base = ((size_t)(bc*NH) + h) * HD * DSTATE;
        float ed = expf(g_alast[bc*NH + h]);
        #pragma unroll
        for (int i = 0; i < 16; i++) {
            int idx = tid + i*512;
            float st = g_states[base + idx];
            g_prev[base + idx] = S[i];
            S[i] = S[i]*ed + st;
        }
    }
}

// ---------------- fused Y kernel: Y_off + Y_diag + D*x per (chunk,head) ----------------
#define Y_SMEM_BYTES ((128*129*2 + 8192 + 128*68 + 256) * 4)   // 200704 B
__global__ void y_kernel(const float* __restrict__ Dv)
{
    extern __shared__ float sm[];
    float* CBp    = sm;                 // [128][129]  (pad -> conflict-free per-lane rows)
    float* Csp    = CBp + 128*129;      // [128][129]
    float* xs     = Csp + 128*129;      // [128][64]  raw x (no dt)
    float* prevT  = xs + 8192;          // [128][68]  prev transposed [n][p]
    float* acum_s = prevT + 128*68;     // [128]
    float* dt_s   = acum_s + 128;       // [128]
    int h  = blockIdx.x % NH;
    int bc = blockIdx.x / NH;
    int tid = threadIdx.x;              // 128
    int row0 = bc * CHUNKQ;

    acum_s[tid] = g_acum[(row0+tid)*NH + h];
    dt_s[tid]   = g_dt[(row0+tid)*NH + h];
    for (int i = tid; i < 128*128; i += 128) {
        int l = i >> 7, c = i & 127;
        CBp[l*129 + c] = g_cb[(size_t)bc*CHUNKQ*CHUNKQ + i];
        Csp[l*129 + c] = g_xbc[(size_t)(row0+l)*DXBC + DIN + DSTATE + c];
    }
    size_t pbase = ((size_t)(bc*NH) + h) * HD * DSTATE;
    for (int i = tid; i < 8192; i += 128) {
        int p = i >> 7, n = i & 127;
        prevT[n*68 + p] = g_prev[pbase + i];
        int l2 = i >> 6, pp = i & 63;
        xs[i] = g_xbc[(size_t)(row0+l2)*DXBC + h*HD + pp];
    }
    __syncthreads();

    int l = tid;
    float la  = acum_s[l];
    float eAl = expf(la);
    float acc[64];
    #pragma unroll
    for (int p = 0; p < 64; p++) acc[p] = 0.f;

    // Y_off (un-scaled): sum_n C[l,n] * prev[p,n]
    for (int n = 0; n < 128; n++) {
        float cv = Csp[l*129 + n];
        const float4* pr = (const float4*)&prevT[n*68];
        #pragma unroll
        for (int p4 = 0; p4 < 16; p4++) {
            float4 v = pr[p4];
            acc[4*p4+0] += cv*v.x; acc[4*p4+1] += cv*v.y;
            acc[4*p4+2] += cv*v.z; acc[4*p4+3] += cv*v.w;
        }
    }
    // scale by exp(Acum[l]) and add D[h]*x[l,p]
    {
        float dval = Dv[h];
        const float4* xr = (const float4*)&xs[l*64];
        #pragma unroll
        for (int p4 = 0; p4 < 16; p4++) {
            float4 v = xr[p4];
            acc[4*p4+0] = acc[4*p4+0]*eAl + dval*v.x;
            acc[4*p4+1] = acc[4*p4+1]*eAl + dval*v.y;
            acc[4*p4+2] = acc[4*p4+2]*eAl + dval*v.z;
            acc[4*p4+3] = acc[4*p4+3]*eAl + dval*v.w;
        }
    }
    // Y_diag: sum_{s<=l} CB[l,s]*exp(Acum[l]-Acum[s])*dt[s]*x[s,p]
    for (int s = 0; s <= l; s++) {
        float w = CBp[l*129 + s] * expf(la - acum_s[s]) * dt_s[s];
        const float4* xv = (const float4*)&xs[s*64];
        #pragma unroll
        for (int p4 = 0; p4 < 16; p4++) {
            float4 v = xv[p4];
            acc[4*p4+0] += w*v.x; acc[4*p4+1] += w*v.y;
            acc[4*p4+2] += w*v.z; acc[4*p4+3] += w*v.w;
        }
    }
    float4* yo = (float4*)&g_y[(size_t)(row0+l)*DIN + h*HD];
    #pragma unroll
    for (int p4 = 0; p4 < 16; p4++)
        yo[p4] = make_float4(acc[4*p4], acc[4*p4+1], acc[4*p4+2], acc[4*p4+3]);
}

// ---------------- gating + RMSNorm ----------------
__global__ void norm_kernel(const float* __restrict__ norm_w)
{
    __shared__ float tbuf[DIN];
    __shared__ float red[256];
    int row = blockIdx.x;
    int tid = threadIdx.x;   // 256
    float partial = 0.f;
    for (int i = tid; i < DIN; i += 256) {
        float yv = g_y[(size_t)row*DIN + i];
        float zv = g_zx[(size_t)row*DPROJ + i];
        float t  = yv * (zv / (1.f + expf(-zv)));
        tbuf[i] = t;
        partial += t*t;
    }
    red[tid] = partial;
    __syncthreads();
    for (int s = 128; s > 0; s >>= 1) {
        if (tid < s) red[tid] += red[tid + s];
        __syncthreads();
    }
    float scale = rsqrtf(red[0] / (float)DIN + 1e-5f);
    for (int i = tid; i < DIN; i += 256)
        g_y[(size_t)row*DIN + i] = tbuf[i] * scale * norm_w[i];
}

// ---------------- launch ----------------
extern "C" void kernel_launch(void* const* d_in, const int* in_sizes, int n_in,
                              void* d_out, int out_size)
{
    const float* feature = (const float*)d_in[0];
    const float* gate1   = (const float*)d_in[1];
    const float* in_w    = (const float*)d_in[2];
    const float* conv_w  = (const float*)d_in[3];
    const float* conv_b  = (const float*)d_in[4];
    const float* dt_bias = (const float*)d_in[5];
    const float* A_log   = (const float*)d_in[6];
    const float* Dv      = (const float*)d_in[7];
    const float* norm_w  = (const float*)d_in[8];
    const float* out_w   = (const float*)d_in[9];
    float* out = (float*)d_out;

    void* p_zx; cudaGetSymbolAddress(&p_zx, g_zx);
    void* p_y;  cudaGetSymbolAddress(&p_y,  g_y);

    cudaFuncSetAttribute(cb_kernel,     cudaFuncAttributeMaxDynamicSharedMemorySize, CB_SMEM_BYTES);
    cudaFuncSetAttribute(states_kernel, cudaFuncAttributeMaxDynamicSharedMemorySize, ST_SMEM_BYTES);
    cudaFuncSetAttribute(y_kernel,      cudaFuncAttributeMaxDynamicSharedMemorySize, Y_SMEM_BYTES);

    // 1. zxbcdt = feature @ in_proj_w^T
    gemm_nt<0><<<dim3((DPROJ + 63)/64, NROWS/64), 256>>>(
        feature, in_w, (float*)p_zx, NROWS, DPROJ, DMODEL, nullptr, nullptr);
    // 2. conv + silu on xBC slice
    conv_silu_kernel<<<(NROWS*DXBC + 255)/256, 256>>>(conv_w, conv_b);
    // 3. dt
    dt_kernel<<<(NROWS*NH + 255)/256, 256>>>(dt_bias);
    // 4. per-chunk cumsum of dt*A
    acum_kernel<<<NBC*NH, CHUNKQ>>>(A_log);
    // 5. CB per chunk
    cb_kernel<<<NBC, 256, CB_SMEM_BYTES>>>();
    // 6. chunk states
    states_kernel<<<NBC*NH, 256, ST_SMEM_BYTES>>>();
    // 7. inter-chunk recurrence
    scan_kernel<<<BSZ*NH, 512>>>();
    // 8. Y = Y_diag + Y_off + D*x
    y_kernel<<<NBC*NH, CHUNKQ, Y_SMEM_BYTES>>>(Dv);
    // 9. gating + RMSNorm
    norm_kernel<<<NROWS, 256>>>(norm_w);
    // 10. out = sigmoid(gate1) * (y @ out_proj_w^T) + feature
    gemm_nt<1><<<dim3(DMODEL/64, NROWS/64), 256>>>(
        (const float*)p_y, out_w, out, NROWS, DMODEL, DIN, feature, gate1);
}

// round 5
// speedup vs baseline: 1.9603x; 1.9603x over previous
#include <cuda_runtime.h>
#include <cuda_bf16.h>
#include <math.h>
#include <stdint.h>

// ---------------- problem constants ----------------
#define BSZ     2
#define SEQL    4096
#define DMODEL  768
#define DSTATE  128
#define HD      64
#define DIN     1536
#define NH      24
#define DXBC    1792          // DIN + 2*DSTATE
#define DPROJ   3352          // 2*DIN + 2*DSTATE + NH
#define CHUNKQ  128
#define NCH     32            // SEQL / CHUNKQ
#define NROWS   (BSZ*SEQL)    // 8192
#define NBC     (BSZ*NCH)     // 64

// GEMM1: M=8192 N=3352(pad 3456) K=768  -> K'=2304
// GEMM2: M=8192 N=768            K=1536 -> K'=4608
#define KP1     (3*DMODEL)    // 2304
#define KP2     (3*DIN)       // 4608
#define NPAD1   3456          // 27*128

// ---------------- scratch (static device memory; no runtime allocs) ----------------
__device__ float g_zx[(size_t)NROWS*DPROJ];
__device__ float g_xbc[(size_t)NROWS*DXBC];
__device__ float g_dt[NROWS*NH];
__device__ float g_acum[NROWS*NH];
__device__ float g_alast[NBC*NH];
__device__ float g_cb[(size_t)NBC*CHUNKQ*CHUNKQ];
__device__ float g_states[(size_t)NBC*NH*HD*DSTATE];
__device__ float g_prev[(size_t)NBC*NH*HD*DSTATE];
__device__ float g_y[(size_t)NROWS*DIN];
__device__ __nv_bfloat16 g_a2[(size_t)NROWS*KP2];      // split A (8192*4608)
__device__ __nv_bfloat16 g_b2[(size_t)NPAD1*KP1];      // split B (3456*2304 > 768*4608? no: 768*4608=3538944 < 7962624 ok)

// ================= helpers (family-target safe: mma.sync / ldmatrix / cp.async) =================
__device__ __forceinline__ uint32_t smem_u32(const void* p) {
    uint32_t a;
    asm("{ .reg .u64 t; cvta.to.shared.u64 t, %1; cvt.u32.u64 %0, t; }" : "=r"(a) : "l"(p));
    return a;
}
__device__ __forceinline__ void cpasync16(uint32_t dst, const void* src) {
    asm volatile("cp.async.cg.shared.global [%0], [%1], 16;" :: "r"(dst), "l"(src) : "memory");
}
__device__ __forceinline__ void ldsm4(uint32_t* r, uint32_t addr) {
    asm volatile("ldmatrix.sync.aligned.m8n8.x4.shared.b16 {%0,%1,%2,%3}, [%4];"
                 : "=r"(r[0]), "=r"(r[1]), "=r"(r[2]), "=r"(r[3]) : "r"(addr));
}
__device__ __forceinline__ void mma16816(float* d, const uint32_t* a, const uint32_t* b,
                                         const float* c) {
    asm volatile("mma.sync.aligned.m16n8k16.row.col.f32.bf16.bf16.f32 "
        "{%0,%1,%2,%3}, {%4,%5,%6,%7}, {%8,%9}, {%10,%11,%12,%13};"
        : "=f"(d[0]), "=f"(d[1]), "=f"(d[2]), "=f"(d[3])
        : "r"(a[0]), "r"(a[1]), "r"(a[2]), "r"(a[3]), "r"(b[0]), "r"(b[1]),
          "f"(c[0]), "f"(c[1]), "f"(c[2]), "f"(c[3]));
}
#define SWZ128(x) ((x) ^ (((x) >> 3) & 0x70))

// ================= split-precision conversion =================
// A' per row: [0:K)=hi, [K:2K)=hi, [2K:3K)=lo
__global__ void split_a_kernel(const float* __restrict__ X, __nv_bfloat16* __restrict__ O,
                               int M, int K)
{
    int idx = blockIdx.x * blockDim.x + threadIdx.x;
    if (idx >= M * K) return;
    int m = idx / K, k = idx % K;
    float x = X[idx];
    __nv_bfloat16 hi = __float2bfloat16(x);
    __nv_bfloat16 lo = __float2bfloat16(x - __bfloat162float(hi));
    size_t base = (size_t)m * 3 * K;
    O[base + k] = hi; O[base + K + k] = hi; O[base + 2*K + k] = lo;
}
// B' per row: [0:K)=hi, [K:2K)=lo, [2K:3K)=hi   (rows >= Nreal zero-padded)
__global__ void split_b_kernel(const float* __restrict__ W, __nv_bfloat16* __restrict__ O,
                               int Nreal, int Npad, int K)
{
    int idx = blockIdx.x * blockDim.x + threadIdx.x;
    if (idx >= Npad * K) return;
    int n = idx / K, k = idx % K;
    __nv_bfloat16 hi = __float2bfloat16(0.f), lo = hi;
    if (n < Nreal) {
        float x = W[(size_t)n * K + k];
        hi = __float2bfloat16(x);
        lo = __float2bfloat16(x - __bfloat162float(hi));
    }
    size_t base = (size_t)n * 3 * K;
    O[base + k] = hi; O[base + K + k] = lo; O[base + 2*K + k] = hi;
}

// ================= mma.sync bf16 GEMM: C[M,Nreal] = A2[M,KP] * B2[Npad,KP]^T =================
// 128x128 CTA tile, 8 warps (2x4), warp tile 64x32, K-chunk 64, cp.async double buffer.
// ep=1: C = sigmoid(gate1)*acc + feat
#define GEMM_SMEM_BYTES (1024 + 2*32768)
__global__ __launch_bounds__(256, 2)
void gemm_mma(const __nv_bfloat16* __restrict__ A2, const __nv_bfloat16* __restrict__ B2,
              float* __restrict__ C, int KP, int Nreal, int ldc,
              const float* __restrict__ feat, const float* __restrict__ gate1, int ep)
{
    extern __shared__ char dsm[];
    const uint32_t base = (smem_u32(dsm) + 1023) & ~1023u;
    const int tid  = threadIdx.x;
    const int lane = tid & 31;
    const int wid  = tid >> 5;
    const int m0 = blockIdx.y * 128;
    const int n0 = blockIdx.x * 128;
    const int wm = wid >> 2;        // 0..1 -> m offset wm*64
    const int wn = wid & 3;         // 0..3 -> n offset wn*32

    // fill mapping: 256 threads, each loads 4x16B for A and B
    const int frow = tid >> 3;      // 0..31 (+ j*32)
    const int u16  = tid & 7;
    const __nv_bfloat16* ag = A2 + (size_t)(m0 + frow) * KP + u16 * 8;
    const __nv_bfloat16* bg = B2 + (size_t)(n0 + frow) * KP + u16 * 8;

    float acc[4][4][4] = {};
    const int nch = KP >> 6;

    // precomputed swizzled fill offsets
    uint32_t foff[4];
    #pragma unroll
    for (int j = 0; j < 4; ++j)
        foff[j] = SWZ128((frow + j*32)*128 + u16*16);

    // stage 0 prologue
    {
        uint32_t ab = base, bb = base + 16384;
        #pragma unroll
        for (int j = 0; j < 4; ++j) {
            cpasync16(ab + foff[j], ag + (size_t)(j*32)*KP);
            cpasync16(bb + foff[j], bg + (size_t)(j*32)*KP);
        }
        asm volatile("cp.async.commit_group;" ::: "memory");
    }

    for (int c = 0; c < nch; ++c) {
        if (c + 1 < nch) {
            uint32_t ab = base + ((c+1)&1) * 32768, bb = ab + 16384;
            const __nv_bfloat16* a = ag + (c+1) * 64;
            const __nv_bfloat16* b = bg + (c+1) * 64;
            #pragma unroll
            for (int j = 0; j < 4; ++j) {
                cpasync16(ab + foff[j], a + (size_t)(j*32)*KP);
                cpasync16(bb + foff[j], b + (size_t)(j*32)*KP);
            }
            asm volatile("cp.async.commit_group;" ::: "memory");
            asm volatile("cp.async.wait_group 1;" ::: "memory");
        } else {
            asm volatile("cp.async.wait_group 0;" ::: "memory");
        }
        __syncthreads();

        const uint32_t ab = base + (c&1) * 32768;
        const uint32_t bb = ab + 16384;
        #pragma unroll
        for (int ks = 0; ks < 4; ++ks) {
            uint32_t a_r[4][4];
            uint32_t b_r[2][4];
            {
                const int ra = wm*64 + ((lane>>3)&1)*8 + (lane&7);
                const int ka = ks*32 + ((lane>>4)&1)*16;
                #pragma unroll
                for (int mf = 0; mf < 4; ++mf)
                    ldsm4(a_r[mf], ab + SWZ128((ra + mf*16)*128 + ka));
            }
            {
                const int rb = wn*32 + ((lane>>4)&1)*8 + (lane&7);
                const int kb = ks*32 + ((lane>>3)&1)*16;
                #pragma unroll
                for (int nf2 = 0; nf2 < 2; ++nf2)
                    ldsm4(b_r[nf2], bb + SWZ128((rb + nf2*16)*128 + kb));
            }
            #pragma unroll
            for (int mf = 0; mf < 4; ++mf)
                #pragma unroll
                for (int nf = 0; nf < 4; ++nf)
                    mma16816(acc[mf][nf], a_r[mf], &b_r[nf>>1][(nf&1)*2], acc[mf][nf]);
        }
        __syncthreads();
    }

    // epilogue
    float g = 0.f;
    if (ep) g = 1.f / (1.f + expf(-gate1[0]));
    const int mrow = m0 + wm*64 + (lane >> 2);
    const int nbase = n0 + wn*32 + (lane & 3)*2;
    #pragma unroll
    for (int mf = 0; mf < 4; ++mf) {
        #pragma unroll
        for (int nf = 0; nf < 4; ++nf) {
            int m = mrow + mf*16;
            int n = nbase + nf*8;
            if (n < Nreal) {
                float2 v0 = make_float2(acc[mf][nf][0], acc[mf][nf][1]);
                float2 v1 = make_float2(acc[mf][nf][2], acc[mf][nf][3]);
                if (ep) {
                    float2 f0 = *(const float2*)(feat + (size_t)m*ldc + n);
                    float2 f1 = *(const float2*)(feat + (size_t)(m+8)*ldc + n);
                    v0.x = g*v0.x + f0.x; v0.y = g*v0.y + f0.y;
                    v1.x = g*v1.x + f1.x; v1.y = g*v1.y + f1.y;
                }
                *(float2*)(C + (size_t)m*ldc + n)     = v0;
                *(float2*)(C + (size_t)(m+8)*ldc + n) = v1;
            }
        }
    }
}

// ---------------- depthwise causal conv (width 4) + bias + SiLU ----------------
__global__ void conv_silu_kernel(const float* __restrict__ cw, const float* __restrict__ cb)
{
    int idx = blockIdx.x * blockDim.x + threadIdx.x;
    if (idx >= NROWS * DXBC) return;
    int ch  = idx % DXBC;
    int row = idx / DXBC;
    int l   = row % SEQL;
    float acc = cb[ch];
    #pragma unroll
    for (int k = 0; k < 4; k++) {
        int ls = l + k - 3;
        if (ls >= 0)
            acc += cw[ch*4 + k] * g_zx[(size_t)(row + k - 3) * DPROJ + DIN + ch];
    }
    g_xbc[idx] = acc / (1.f + expf(-acc));   // silu
}

// ---------------- dt = softplus(raw + dt_bias) ----------------
__global__ void dt_kernel(const float* __restrict__ dt_bias)
{
    int idx = blockIdx.x * blockDim.x + threadIdx.x;
    if (idx >= NROWS * NH) return;
    int h   = idx % NH;
    int row = idx / NH;
    float v = g_zx[(size_t)row * DPROJ + (DIN + DXBC) + h] + dt_bias[h];
    g_dt[idx] = (v > 20.f) ? v : log1pf(expf(v));
}

// ---------------- per-chunk inclusive cumsum of Adt = dt * (-exp(A_log)) ----------------
__global__ void acum_kernel(const float* __restrict__ A_log)
{
    int h  = blockIdx.x % NH;
    int bc = blockIdx.x / NH;
    int l  = threadIdx.x;   // 128
    __shared__ float s[CHUNKQ];
    float Ah = -expf(A_log[h]);
    int row = bc * CHUNKQ + l;
    s[l] = g_dt[row * NH + h] * Ah;
    __syncthreads();
    for (int off = 1; off < CHUNKQ; off <<= 1) {
        float v = (l >= off) ? s[l - off] : 0.f;
        __syncthreads();
        s[l] += v;
        __syncthreads();
    }
    g_acum[row * NH + h] = s[l];
    if (l == CHUNKQ - 1) g_alast[bc * NH + h] = s[l];
}

// ---------------- CB[l,s] = sum_n C[l,n]*B[s,n] per chunk ----------------
#define CB_SMEM_BYTES ((CHUNKQ*CHUNKQ + CHUNKQ*132) * 4)
__global__ void cb_kernel()
{
    extern __shared__ float sm[];
    float* Cs  = sm;                    // [128][128]  l-major
    float* BsT = sm + CHUNKQ*CHUNKQ;    // [128][132]  n-major (transposed, padded)
    int bc  = blockIdx.x;
    int tid = threadIdx.x;              // 256
    int row0 = bc * CHUNKQ;
    for (int i = tid; i < CHUNKQ*CHUNKQ; i += 256) {
        int l = i >> 7, n = i & 127;
        const float* base = &g_xbc[(size_t)(row0 + l) * DXBC];
        Cs[i]            = base[DIN + DSTATE + n];
        BsT[n*132 + l]   = base[DIN + n];
    }
    __syncthreads();
    int l  = tid >> 1;
    int s0 = (tid & 1) * 64;
    float acc[64] = {};
    for (int n = 0; n < 128; n++) {
        float cv = Cs[l*128 + n];
        const float4* bp = (const float4*)&BsT[n*132 + s0];
        #pragma unroll
        for (int j4 = 0; j4 < 16; j4++) {
            float4 b = bp[j4];
            acc[4*j4+0] += cv*b.x; acc[4*j4+1] += cv*b.y;
            acc[4*j4+2] += cv*b.z; acc[4*j4+3] += cv*b.w;
        }
    }
    float* outp = &g_cb[(size_t)bc*CHUNKQ*CHUNKQ + l*CHUNKQ + s0];
    #pragma unroll
    for (int j4 = 0; j4 < 16; j4++)
        ((float4*)outp)[j4] = make_float4(acc[4*j4], acc[4*j4+1], acc[4*j4+2], acc[4*j4+3]);
}

// ---------------- states[p,n] = sum_l dt[l]*exp(Alast-Acum[l]) * x[l,p] * B[l,n] ----------------
#define ST_SMEM_BYTES ((128 + 8192 + 16384) * 4)
__global__ void states_kernel()
{
    extern __shared__ float sm[];
    float* wfac = sm;            // [128]
    float* xw   = sm + 128;      // [128][64]
    float* Bsm  = xw + 8192;     // [128][128]
    int h  = blockIdx.x % NH;
    int bc = blockIdx.x / NH;
    int tid = threadIdx.x;       // 256
    int row0 = bc * CHUNKQ;
    float alast = g_alast[bc*NH + h];
    if (tid < 128)
        wfac[tid] = g_dt[(row0+tid)*NH + h] * expf(alast - g_acum[(row0+tid)*NH + h]);
    __syncthreads();
    for (int i = tid; i < 8192; i += 256) {
        int l = i >> 6, p = i & 63;
        xw[i] = g_xbc[(size_t)(row0+l)*DXBC + h*HD + p] * wfac[l];
    }
    for (int i = tid; i < 16384; i += 256) {
        int l = i >> 7, n = i & 127;
        Bsm[i] = g_xbc[(size_t)(row0+l)*DXBC + DIN + n];
    }
    __syncthreads();
    int tp = tid >> 4, tn = tid & 15;
    int p0 = tp*4, n0 = tn*8;
    float acc[4][8] = {};
    for (int l = 0; l < 128; l++) {
        float4 a  = *(const float4*)&xw[l*64 + p0];
        float4 b0 = *(const float4*)&Bsm[l*128 + n0];
        float4 b1 = *(const float4*)&Bsm[l*128 + n0 + 4];
        float av[4] = {a.x, a.y, a.z, a.w};
        float bv[8] = {b0.x, b0.y, b0.z, b0.w, b1.x, b1.y, b1.z, b1.w};
        #pragma unroll
        for (int i = 0; i < 4; i++)
            #pragma unroll
            for (int j = 0; j < 8; j++)
                acc[i][j] += av[i] * bv[j];
    }
    float* outb = &g_states[((size_t)(bc*NH) + h) * HD * DSTATE];
    #pragma unroll
    for (int i = 0; i < 4; i++) {
        *(float4*)&outb[(p0+i)*DSTATE + n0]     = make_float4(acc[i][0], acc[i][1], acc[i][2], acc[i][3]);
        *(float4*)&outb[(p0+i)*DSTATE + n0 + 4] = make_float4(acc[i][4], acc[i][5], acc[i][6], acc[i][7]);
    }
}

// ---------------- inter-chunk state recurrence ----------------
__global__ void scan_kernel()
{
    int h = blockIdx.x % NH;
    int b = blockIdx.x / NH;
    int tid = threadIdx.x;   // 512
    float S[16];
    #pragma unroll
    for (int i = 0; i < 16; i++) S[i] = 0.f;
    for (int c = 0; c < NCH; c++) {
        int bc = b*NCH + c;
        size_t base = ((size_t)(bc*NH) + h) * HD * DSTATE;
        float ed = expf(g_alast[bc*NH + h]);
        #pragma unroll
        for (int i = 0; i < 16; i++) {
            int idx = tid + i*512;
            float st = g_states[base + idx];
            g_prev[base + idx] = S[i];
            S[i] = S[i]*ed + st;
        }
    }
}

// ---------------- fused Y kernel ----------------
#define Y_SMEM_BYTES ((128*129*2 + 8192 + 128*68 + 256) * 4)
__global__ void y_kernel(const float* __restrict__ Dv)
{
    extern __shared__ float sm[];
    float* CBp    = sm;
    float* Csp    = CBp + 128*129;
    float* xs     = Csp + 128*129;
    float* prevT  = xs + 8192;
    float* acum_s = prevT + 128*68;
    float* dt_s   = acum_s + 128;
    int h  = blockIdx.x % NH;
    int bc = blockIdx.x / NH;
    int tid = threadIdx.x;              // 128
    int row0 = bc * CHUNKQ;

    acum_s[tid] = g_acum[(row0+tid)*NH + h];
    dt_s[tid]   = g_dt[(row0+tid)*NH + h];
    for (int i = tid; i < 128*128; i += 128) {
        int l = i >> 7, c = i & 127;
        CBp[l*129 + c] = g_cb[(size_t)bc*CHUNKQ*CHUNKQ + i];
        Csp[l*129 + c] = g_xbc[(size_t)(row0+l)*DXBC + DIN + DSTATE + c];
    }
    size_t pbase = ((size_t)(bc*NH) + h) * HD * DSTATE;
    for (int i = tid; i < 8192; i += 128) {
        int p = i >> 7, n = i & 127;
        prevT[n*68 + p] = g_prev[pbase + i];
        int l2 = i >> 6, pp = i & 63;
        xs[i] = g_xbc[(size_t)(row0+l2)*DXBC + h*HD + pp];
    }
    __syncthreads();

    int l = tid;
    float la  = acum_s[l];
    float eAl = expf(la);
    float acc[64];
    #pragma unroll
    for (int p = 0; p < 64; p++) acc[p] = 0.f;

    for (int n = 0; n < 128; n++) {
        float cv = Csp[l*129 + n];
        const float4* pr = (const float4*)&prevT[n*68];
        #pragma unroll
        for (int p4 = 0; p4 < 16; p4++) {
            float4 v = pr[p4];
            acc[4*p4+0] += cv*v.x; acc[4*p4+1] += cv*v.y;
            acc[4*p4+2] += cv*v.z; acc[4*p4+3] += cv*v.w;
        }
    }
    {
        float dval = Dv[h];
        const float4* xr = (const float4*)&xs[l*64];
        #pragma unroll
        for (int p4 = 0; p4 < 16; p4++) {
            float4 v = xr[p4];
            acc[4*p4+0] = acc[4*p4+0]*eAl + dval*v.x;
            acc[4*p4+1] = acc[4*p4+1]*eAl + dval*v.y;
            acc[4*p4+2] = acc[4*p4+2]*eAl + dval*v.z;
            acc[4*p4+3] = acc[4*p4+3]*eAl + dval*v.w;
        }
    }
    for (int s = 0; s <= l; s++) {
        float w = CBp[l*129 + s] * expf(la - acum_s[s]) * dt_s[s];
        const float4* xv = (const float4*)&xs[s*64];
        #pragma unroll
        for (int p4 = 0; p4 < 16; p4++) {
            float4 v = xv[p4];
            acc[4*p4+0] += w*v.x; acc[4*p4+1] += w*v.y;
            acc[4*p4+2] += w*v.z; acc[4*p4+3] += w*v.w;
        }
    }
    float4* yo = (float4*)&g_y[(size_t)(row0+l)*DIN + h*HD];
    #pragma unroll
    for (int p4 = 0; p4 < 16; p4++)
        yo[p4] = make_float4(acc[4*p4], acc[4*p4+1], acc[4*p4+2], acc[4*p4+3]);
}

// ---------------- gating + RMSNorm ----------------
__global__ void norm_kernel(const float* __restrict__ norm_w)
{
    __shared__ float tbuf[DIN];
    __shared__ float red[256];
    int row = blockIdx.x;
    int tid = threadIdx.x;   // 256
    float partial = 0.f;
    for (int i = tid; i < DIN; i += 256) {
        float yv = g_y[(size_t)row*DIN + i];
        float zv = g_zx[(size_t)row*DPROJ + i];
        float t  = yv * (zv / (1.f + expf(-zv)));
        tbuf[i] = t;
        partial += t*t;
    }
    red[tid] = partial;
    __syncthreads();
    for (int s = 128; s > 0; s >>= 1) {
        if (tid < s) red[tid] += red[tid + s];
        __syncthreads();
    }
    float scale = rsqrtf(red[0] / (float)DIN + 1e-5f);
    for (int i = tid; i < DIN; i += 256)
        g_y[(size_t)row*DIN + i] = tbuf[i] * scale * norm_w[i];
}

// ---------------- launch ----------------
extern "C" void kernel_launch(void* const* d_in, const int* in_sizes, int n_in,
                              void* d_out, int out_size)
{
    const float* feature = (const float*)d_in[0];
    const float* gate1   = (const float*)d_in[1];
    const float* in_w    = (const float*)d_in[2];
    const float* conv_w  = (const float*)d_in[3];
    const float* conv_b  = (const float*)d_in[4];
    const float* dt_bias = (const float*)d_in[5];
    const float* A_log   = (const float*)d_in[6];
    const float* Dv      = (const float*)d_in[7];
    const float* norm_w  = (const float*)d_in[8];
    const float* out_w   = (const float*)d_in[9];
    float* out = (float*)d_out;

    void* p_zx; cudaGetSymbolAddress(&p_zx, g_zx);
    void* p_y;  cudaGetSymbolAddress(&p_y,  g_y);
    void* p_a2; cudaGetSymbolAddress(&p_a2, g_a2);
    void* p_b2; cudaGetSymbolAddress(&p_b2, g_b2);
    __nv_bfloat16* a2 = (__nv_bfloat16*)p_a2;
    __nv_bfloat16* b2 = (__nv_bfloat16*)p_b2;

    cudaFuncSetAttribute(cb_kernel,     cudaFuncAttributeMaxDynamicSharedMemorySize, CB_SMEM_BYTES);
    cudaFuncSetAttribute(states_kernel, cudaFuncAttributeMaxDynamicSharedMemorySize, ST_SMEM_BYTES);
    cudaFuncSetAttribute(y_kernel,      cudaFuncAttributeMaxDynamicSharedMemorySize, Y_SMEM_BYTES);
    cudaFuncSetAttribute(gemm_mma,      cudaFuncAttributeMaxDynamicSharedMemorySize, GEMM_SMEM_BYTES);

    // 1. split-precision conversion for GEMM1
    split_a_kernel<<<(NROWS*DMODEL + 255)/256, 256>>>(feature, a2, NROWS, DMODEL);
    split_b_kernel<<<(NPAD1*DMODEL + 255)/256, 256>>>(in_w, b2, DPROJ, NPAD1, DMODEL);
    // 2. zxbcdt = feature @ in_proj_w^T  (tensor cores, mma.sync)
    gemm_mma<<<dim3(NPAD1/128, NROWS/128), 256, GEMM_SMEM_BYTES>>>(
        a2, b2, (float*)p_zx, KP1, DPROJ, DPROJ, nullptr, nullptr, 0);
    // 3. conv + silu
    conv_silu_kernel<<<(NROWS*DXBC + 255)/256, 256>>>(conv_w, conv_b);
    // 4. dt
    dt_kernel<<<(NROWS*NH + 255)/256, 256>>>(dt_bias);
    // 5. per-chunk cumsum
    acum_kernel<<<NBC*NH, CHUNKQ>>>(A_log);
    // 6. CB per chunk
    cb_kernel<<<NBC, 256, CB_SMEM_BYTES>>>();
    // 7. chunk states
    states_kernel<<<NBC*NH, 256, ST_SMEM_BYTES>>>();
    // 8. inter-chunk recurrence
    scan_kernel<<<BSZ*NH, 512>>>();
    // 9. Y = Y_diag + Y_off + D*x
    y_kernel<<<NBC*NH, CHUNKQ, Y_SMEM_BYTES>>>(Dv);
    // 10. gating + RMSNorm
    norm_kernel<<<NROWS, 256>>>(norm_w);
    // 11. split-precision conversion for GEMM2
    split_a_kernel<<<(NROWS*DIN + 255)/256, 256>>>((const float*)p_y, a2, NROWS, DIN);
    split_b_kernel<<<(DMODEL*DIN + 255)/256, 256>>>(out_w, b2, DMODEL, DMODEL, DIN);
    // 12. out = sigmoid(gate1) * (y @ out_proj_w^T) + feature  (tensor cores)
    gemm_mma<<<dim3(DMODEL/128, NROWS/128), 256, GEMM_SMEM_BYTES>>>(
        a2, b2, out, KP2, DMODEL, DMODEL, feature, gate1, 1);
}

// round 7
// speedup vs baseline: 2.6947x; 1.3746x over previous
#include <cuda_runtime.h>
#include <cuda_bf16.h>
#include <math.h>
#include <stdint.h>

// ---------------- problem constants ----------------
#define BSZ     2
#define SEQL    4096
#define DMODEL  768
#define DSTATE  128
#define HD      64
#define DIN     1536
#define NH      24
#define DXBC    1792          // DIN + 2*DSTATE
#define DPROJ   3352          // 2*DIN + 2*DSTATE + NH
#define CHUNKQ  128
#define NCH     32            // SEQL / CHUNKQ
#define NROWS   (BSZ*SEQL)    // 8192
#define NBC     (BSZ*NCH)     // 64

#define KP1     (3*DMODEL)    // 2304
#define KP2     (3*DIN)       // 4608
#define NPAD1   3456          // 27*128

// single shared-memory extern symbol (consistent across all kernels)
extern __shared__ __align__(128) char smbuf[];

// ---------------- scratch (static device memory; no runtime allocs) ----------------
__device__ float g_zx[(size_t)NROWS*DPROJ];
__device__ float g_xbc[(size_t)NROWS*DXBC];
__device__ float g_dt[NROWS*NH];
__device__ float g_acum[NROWS*NH];
__device__ float g_alast[NBC*NH];
__device__ float g_cb[(size_t)NBC*CHUNKQ*CHUNKQ];
__device__ float g_states[(size_t)NBC*NH*HD*DSTATE];
__device__ float g_prev[(size_t)NBC*NH*HD*DSTATE];
__device__ float g_y[(size_t)NROWS*DIN];
__device__ __nv_bfloat16 g_a2[(size_t)NROWS*KP2];
__device__ __nv_bfloat16 g_b2[(size_t)NPAD1*KP1];

// ================= helpers (family-target safe) =================
__device__ __forceinline__ uint32_t smem_u32(const void* p) {
    uint32_t a;
    asm("{ .reg .u64 t; cvta.to.shared.u64 t, %1; cvt.u32.u64 %0, t; }" : "=r"(a) : "l"(p));
    return a;
}
__device__ __forceinline__ void cpasync16(uint32_t dst, const void* src) {
    asm volatile("cp.async.cg.shared.global [%0], [%1], 16;" :: "r"(dst), "l"(src) : "memory");
}
__device__ __forceinline__ void ldsm4(uint32_t* r, uint32_t addr) {
    asm volatile("ldmatrix.sync.aligned.m8n8.x4.shared.b16 {%0,%1,%2,%3}, [%4];"
                 : "=r"(r[0]), "=r"(r[1]), "=r"(r[2]), "=r"(r[3]) : "r"(addr));
}
__device__ __forceinline__ void mma16816(float* d, const uint32_t* a, const uint32_t* b,
                                         const float* c) {
    asm volatile("mma.sync.aligned.m16n8k16.row.col.f32.bf16.bf16.f32 "
        "{%0,%1,%2,%3}, {%4,%5,%6,%7}, {%8,%9}, {%10,%11,%12,%13};"
        : "=f"(d[0]), "=f"(d[1]), "=f"(d[2]), "=f"(d[3])
        : "r"(a[0]), "r"(a[1]), "r"(a[2]), "r"(a[3]), "r"(b[0]), "r"(b[1]),
          "f"(c[0]), "f"(c[1]), "f"(c[2]), "f"(c[3]));
}
#define SWZ128(x) ((x) ^ (((x) >> 3) & 0x70))
// swizzle for 256-byte rows (128 bf16 per row)
#define SWZ256(x) ((x) ^ (((x) >> 4) & 0x70))

__device__ __forceinline__ void split_store(char* hi_base, char* lo_base, uint32_t off, float v) {
    __nv_bfloat16 hi = __float2bfloat16(v);
    __nv_bfloat16 lo = __float2bfloat16(v - __bfloat162float(hi));
    *(__nv_bfloat16*)(hi_base + off) = hi;
    *(__nv_bfloat16*)(lo_base + off) = lo;
}

// ================= split-precision conversion for big GEMMs =================
__global__ void split_a_kernel(const float* __restrict__ X, __nv_bfloat16* __restrict__ O,
                               int M, int K)
{
    int idx = blockIdx.x * blockDim.x + threadIdx.x;
    if (idx >= M * K) return;
    int m = idx / K, k = idx % K;
    float x = X[idx];
    __nv_bfloat16 hi = __float2bfloat16(x);
    __nv_bfloat16 lo = __float2bfloat16(x - __bfloat162float(hi));
    size_t base = (size_t)m * 3 * K;
    O[base + k] = hi; O[base + K + k] = hi; O[base + 2*K + k] = lo;
}
__global__ void split_b_kernel(const float* __restrict__ W, __nv_bfloat16* __restrict__ O,
                               int Nreal, int Npad, int K)
{
    int idx = blockIdx.x * blockDim.x + threadIdx.x;
    if (idx >= Npad * K) return;
    int n = idx / K, k = idx % K;
    __nv_bfloat16 hi = __float2bfloat16(0.f), lo = hi;
    if (n < Nreal) {
        float x = W[(size_t)n * K + k];
        hi = __float2bfloat16(x);
        lo = __float2bfloat16(x - __bfloat162float(hi));
    }
    size_t base = (size_t)n * 3 * K;
    O[base + k] = hi; O[base + K + k] = lo; O[base + 2*K + k] = hi;
}

// ================= mma.sync bf16 GEMM (verified in R5) =================
#define GEMM_SMEM_BYTES (1024 + 2*32768)
__global__ __launch_bounds__(256, 2)
void gemm_mma(const __nv_bfloat16* __restrict__ A2, const __nv_bfloat16* __restrict__ B2,
              float* __restrict__ C, int KP, int Nreal, int ldc,
              const float* __restrict__ feat, const float* __restrict__ gate1, int ep)
{
    const uint32_t base = (smem_u32(smbuf) + 1023) & ~1023u;
    const int tid  = threadIdx.x;
    const int lane = tid & 31;
    const int wid  = tid >> 5;
    const int m0 = blockIdx.y * 128;
    const int n0 = blockIdx.x * 128;
    const int wm = wid >> 2;
    const int wn = wid & 3;

    const int frow = tid >> 3;
    const int u16  = tid & 7;
    const __nv_bfloat16* ag = A2 + (size_t)(m0 + frow) * KP + u16 * 8;
    const __nv_bfloat16* bg = B2 + (size_t)(n0 + frow) * KP + u16 * 8;

    float acc[4][4][4] = {};
    const int nch = KP >> 6;

    uint32_t foff[4];
    #pragma unroll
    for (int j = 0; j < 4; ++j)
        foff[j] = SWZ128((frow + j*32)*128 + u16*16);

    {
        uint32_t ab = base, bb = base + 16384;
        #pragma unroll
        for (int j = 0; j < 4; ++j) {
            cpasync16(ab + foff[j], ag + (size_t)(j*32)*KP);
            cpasync16(bb + foff[j], bg + (size_t)(j*32)*KP);
        }
        asm volatile("cp.async.commit_group;" ::: "memory");
    }

    for (int c = 0; c < nch; ++c) {
        if (c + 1 < nch) {
            uint32_t ab = base + ((c+1)&1) * 32768, bb = ab + 16384;
            const __nv_bfloat16* a = ag + (c+1) * 64;
            const __nv_bfloat16* b = bg + (c+1) * 64;
            #pragma unroll
            for (int j = 0; j < 4; ++j) {
                cpasync16(ab + foff[j], a + (size_t)(j*32)*KP);
                cpasync16(bb + foff[j], b + (size_t)(j*32)*KP);
            }
            asm volatile("cp.async.commit_group;" ::: "memory");
            asm volatile("cp.async.wait_group 1;" ::: "memory");
        } else {
            asm volatile("cp.async.wait_group 0;" ::: "memory");
        }
        __syncthreads();

        const uint32_t ab = base + (c&1) * 32768;
        const uint32_t bb = ab + 16384;
        #pragma unroll
        for (int ks = 0; ks < 4; ++ks) {
            uint32_t a_r[4][4];
            uint32_t b_r[2][4];
            {
                const int ra = wm*64 + ((lane>>3)&1)*8 + (lane&7);
                const int ka = ks*32 + ((lane>>4)&1)*16;
                #pragma unroll
                for (int mf = 0; mf < 4; ++mf)
                    ldsm4(a_r[mf], ab + SWZ128((ra + mf*16)*128 + ka));
            }
            {
                const int rb = wn*32 + ((lane>>4)&1)*8 + (lane&7);
                const int kb = ks*32 + ((lane>>3)&1)*16;
                #pragma unroll
                for (int nf2 = 0; nf2 < 2; ++nf2)
                    ldsm4(b_r[nf2], bb + SWZ128((rb + nf2*16)*128 + kb));
            }
            #pragma unroll
            for (int mf = 0; mf < 4; ++mf)
                #pragma unroll
                for (int nf = 0; nf < 4; ++nf)
                    mma16816(acc[mf][nf], a_r[mf], &b_r[nf>>1][(nf&1)*2], acc[mf][nf]);
        }
        __syncthreads();
    }

    float g = 0.f;
    if (ep) g = 1.f / (1.f + expf(-gate1[0]));
    const int mrow = m0 + wm*64 + (lane >> 2);
    const int nbase = n0 + wn*32 + (lane & 3)*2;
    #pragma unroll
    for (int mf = 0; mf < 4; ++mf) {
        #pragma unroll
        for (int nf = 0; nf < 4; ++nf) {
            int m = mrow + mf*16;
            int n = nbase + nf*8;
            if (n < Nreal) {
                float2 v0 = make_float2(acc[mf][nf][0], acc[mf][nf][1]);
                float2 v1 = make_float2(acc[mf][nf][2], acc[mf][nf][3]);
                if (ep) {
                    float2 f0 = *(const float2*)(feat + (size_t)m*ldc + n);
                    float2 f1 = *(const float2*)(feat + (size_t)(m+8)*ldc + n);
                    v0.x = g*v0.x + f0.x; v0.y = g*v0.y + f0.y;
                    v1.x = g*v1.x + f1.x; v1.y = g*v1.y + f1.y;
                }
                *(float2*)(C + (size_t)m*ldc + n)     = v0;
                *(float2*)(C + (size_t)(m+8)*ldc + n) = v1;
            }
        }
    }
}

// ---------------- depthwise causal conv (width 4) + bias + SiLU ----------------
__global__ void conv_silu_kernel(const float* __restrict__ cw, const float* __restrict__ cb)
{
    int idx = blockIdx.x * blockDim.x + threadIdx.x;
    if (idx >= NROWS * DXBC) return;
    int ch  = idx % DXBC;
    int row = idx / DXBC;
    int l   = row % SEQL;
    float acc = cb[ch];
    #pragma unroll
    for (int k = 0; k < 4; k++) {
        int ls = l + k - 3;
        if (ls >= 0)
            acc += cw[ch*4 + k] * g_zx[(size_t)(row + k - 3) * DPROJ + DIN + ch];
    }
    g_xbc[idx] = acc / (1.f + __expf(-acc));
}

// ---------------- dt = softplus(raw + dt_bias) ----------------
__global__ void dt_kernel(const float* __restrict__ dt_bias)
{
    int idx = blockIdx.x * blockDim.x + threadIdx.x;
    if (idx >= NROWS * NH) return;
    int h   = idx % NH;
    int row = idx / NH;
    float v = g_zx[(size_t)row * DPROJ + (DIN + DXBC) + h] + dt_bias[h];
    g_dt[idx] = (v > 20.f) ? v : log1pf(expf(v));
}

// ---------------- per-chunk inclusive cumsum of dt*A ----------------
__global__ void acum_kernel(const float* __restrict__ A_log)
{
    int h  = blockIdx.x % NH;
    int bc = blockIdx.x / NH;
    int l  = threadIdx.x;
    __shared__ float s[CHUNKQ];
    float Ah = -expf(A_log[h]);
    int row = bc * CHUNKQ + l;
    s[l] = g_dt[row * NH + h] * Ah;
    __syncthreads();
    for (int off = 1; off < CHUNKQ; off <<= 1) {
        float v = (l >= off) ? s[l - off] : 0.f;
        __syncthreads();
        s[l] += v;
        __syncthreads();
    }
    g_acum[row * NH + h] = s[l];
    if (l == CHUNKQ - 1) g_alast[bc * NH + h] = s[l];
}

// ---------------- CB[l,s] = sum_n C[l,n]*B[s,n] per chunk (fp32, feeds W) ----------------
#define CB_SMEM_BYTES ((CHUNKQ*CHUNKQ + CHUNKQ*132) * 4)
__global__ void cb_kernel()
{
    float* sm  = (float*)smbuf;
    float* Cs  = sm;
    float* BsT = sm + CHUNKQ*CHUNKQ;
    int bc  = blockIdx.x;
    int tid = threadIdx.x;
    int row0 = bc * CHUNKQ;
    for (int i = tid; i < CHUNKQ*CHUNKQ; i += 256) {
        int l = i >> 7, n = i & 127;
        const float* base = &g_xbc[(size_t)(row0 + l) * DXBC];
        Cs[i]            = base[DIN + DSTATE + n];
        BsT[n*132 + l]   = base[DIN + n];
    }
    __syncthreads();
    int l  = tid >> 1;
    int s0 = (tid & 1) * 64;
    float acc[64] = {};
    for (int n = 0; n < 128; n++) {
        float cv = Cs[l*128 + n];
        const float4* bp = (const float4*)&BsT[n*132 + s0];
        #pragma unroll
        for (int j4 = 0; j4 < 16; j4++) {
            float4 b = bp[j4];
            acc[4*j4+0] += cv*b.x; acc[4*j4+1] += cv*b.y;
            acc[4*j4+2] += cv*b.z; acc[4*j4+3] += cv*b.w;
        }
    }
    float* outp = &g_cb[(size_t)bc*CHUNKQ*CHUNKQ + l*CHUNKQ + s0];
    #pragma unroll
    for (int j4 = 0; j4 < 16; j4++)
        ((float4*)outp)[j4] = make_float4(acc[4*j4], acc[4*j4+1], acc[4*j4+2], acc[4*j4+3]);
}

// ================= states via mma.sync (split bf16) =================
// out[p,n] = sum_l (x[l,p]*dt[l]*exp(alast-acum[l])) * B[l,n]
// smem: Ahi[64][128]@0, Alo@16K, Bhi[128][128]@32K, Blo@64K  (256B rows, SWZ256)
#define STM_SMEM_BYTES 98304
__global__ __launch_bounds__(128, 2) void states_mma()
{
    char* sm = smbuf;
    __shared__ float wfac[128];
    const int h  = blockIdx.x % NH;
    const int bc = blockIdx.x / NH;
    const int tid = threadIdx.x;
    const int row0 = bc * CHUNKQ;

    if (tid < 128) {
        float alast = g_alast[bc*NH + h];
        wfac[tid] = g_dt[(row0+tid)*NH + h] * __expf(alast - g_acum[(row0+tid)*NH + h]);
    }
    __syncthreads();
    // A tile (transposed scatter): A[p][l] = x[l,p]*wfac[l]
    for (int i = tid; i < 8192; i += 128) {
        int l = i >> 6, p = i & 63;
        float v = g_xbc[(size_t)(row0+l)*DXBC + h*HD + p] * wfac[l];
        split_store(sm, sm + 16384, SWZ256(p*256 + l*2), v);
    }
    // B tile (transposed scatter): Bt[n][l] = B[l,n]
    for (int i = tid; i < 16384; i += 128) {
        int l = i >> 7, n = i & 127;
        float v = g_xbc[(size_t)(row0+l)*DXBC + DIN + n];
        split_store(sm + 32768, sm + 65536, SWZ256(n*256 + l*2), v);
    }
    __syncthreads();

    const int lane = tid & 31;
    const int w = tid >> 5;                 // 4 warps, warp n-offset w*32
    const uint32_t base = smem_u32(sm);
    float acc[4][4][4] = {};
    const uint32_t AO[3] = {0u, 0u, 16384u};
    const uint32_t BO[3] = {32768u, 65536u, 32768u};
    #pragma unroll
    for (int pp = 0; pp < 3; ++pp) {
        const uint32_t ab = base + AO[pp], bb = base + BO[pp];
        #pragma unroll
        for (int ks = 0; ks < 8; ++ks) {
            uint32_t a_r[4][4], b_r[2][4];
            const int ra = ((lane>>3)&1)*8 + (lane&7);
            const int ca = ks*32 + ((lane>>4)&1)*16;
            #pragma unroll
            for (int mf = 0; mf < 4; ++mf)
                ldsm4(a_r[mf], ab + SWZ256((ra + mf*16)*256 + ca));
            const int rb = w*32 + ((lane>>4)&1)*8 + (lane&7);
            const int cb2 = ks*32 + ((lane>>3)&1)*16;
            #pragma unroll
            for (int nf2 = 0; nf2 < 2; ++nf2)
                ldsm4(b_r[nf2], bb + SWZ256((rb + nf2*16)*256 + cb2));
            #pragma unroll
            for (int mf = 0; mf < 4; ++mf)
                #pragma unroll
                for (int nf = 0; nf < 4; ++nf)
                    mma16816(acc[mf][nf], a_r[mf], &b_r[nf>>1][(nf&1)*2], acc[mf][nf]);
        }
    }
    float* outb = &g_states[((size_t)(bc*NH) + h) * HD * DSTATE];
    const int mr = lane >> 2;
    const int nb = w*32 + (lane & 3)*2;
    #pragma unroll
    for (int mf = 0; mf < 4; ++mf) {
        #pragma unroll
        for (int nf = 0; nf < 4; ++nf) {
            int p = mf*16 + mr, n = nb + nf*8;
            *(float2*)&outb[p*DSTATE + n]       = make_float2(acc[mf][nf][0], acc[mf][nf][1]);
            *(float2*)&outb[(p+8)*DSTATE + n]   = make_float2(acc[mf][nf][2], acc[mf][nf][3]);
        }
    }
}

// ---------------- inter-chunk state recurrence (one lane per thread) ----------------
__global__ void scan_kernel()
{
    int gl = blockIdx.x * blockDim.x + threadIdx.x;  // 0..393215
    int bh = gl >> 13;                               // (b,h)
    int b = bh / NH, h = bh % NH;
    int e = gl & 8191;
    float S = 0.f;
    for (int c = 0; c < NCH; c++) {
        int bc = b*NCH + c;
        size_t base = ((size_t)(bc*NH) + h) * HD * DSTATE;
        float ed = __expf(g_alast[bc*NH + h]);
        float st = g_states[base + e];
        g_prev[base + e] = S;
        S = S*ed + st;
    }
}

// ================= Y via mma.sync (split bf16) =================
// Y[l,p] = exp(acum[l])*sum_n C[l,n]*prev[p,n]  +  sum_{s<=l} W[l,s]*x[s,p]  +  D*x[l,p]
// smem: Ahi[128][128]@0, Alo@32K, Bhi[64][128]@64K, Blo@80K  (256B rows, SWZ256)
#define YM_SMEM_BYTES 98304
__device__ __forceinline__ void y_mma_block(float acc[2][4][4], uint32_t base,
                                            int lane, int wm, int wn)
{
    const uint32_t AO[3] = {0u, 0u, 32768u};
    const uint32_t BO[3] = {65536u, 81920u, 65536u};
    #pragma unroll
    for (int pp = 0; pp < 3; ++pp) {
        const uint32_t ab = base + AO[pp], bb = base + BO[pp];
        #pragma unroll
        for (int ks = 0; ks < 8; ++ks) {
            uint32_t a_r[2][4], b_r[2][4];
            const int ra = wm*32 + ((lane>>3)&1)*8 + (lane&7);
            const int ca = ks*32 + ((lane>>4)&1)*16;
            #pragma unroll
            for (int mf = 0; mf < 2; ++mf)
                ldsm4(a_r[mf], ab + SWZ256((ra + mf*16)*256 + ca));
            const int rb = wn*32 + ((lane>>4)&1)*8 + (lane&7);
            const int cb2 = ks*32 + ((lane>>3)&1)*16;
            #pragma unroll
            for (int nf2 = 0; nf2 < 2; ++nf2)
                ldsm4(b_r[nf2], bb + SWZ256((rb + nf2*16)*256 + cb2));
            #pragma unroll
            for (int mf = 0; mf < 2; ++mf)
                #pragma unroll
                for (int nf = 0; nf < 4; ++nf)
                    mma16816(acc[mf][nf], a_r[mf], &b_r[nf>>1][(nf&1)*2], acc[mf][nf]);
        }
    }
}

__global__ __launch_bounds__(256, 2) void y_mma(const float* __restrict__ Dv)
{
    char* sm = smbuf;
    __shared__ float acum_s[128], dt_s[128], eAl_s[128];
    const int h  = blockIdx.x % NH;
    const int bc = blockIdx.x / NH;
    const int tid = threadIdx.x;
    const int row0 = bc * CHUNKQ;

    if (tid < 128) {
        float a = g_acum[(row0+tid)*NH + h];
        acum_s[tid] = a;
        eAl_s[tid]  = __expf(a);
        dt_s[tid]   = g_dt[(row0+tid)*NH + h];
    }
    __syncthreads();

    // ---- pass 1 tiles: A = C*exp(acum[l]) [l][n], B = prev [p][n]
    for (int i = tid; i < 16384; i += 256) {
        int l = i >> 7, n = i & 127;
        float v = g_xbc[(size_t)(row0+l)*DXBC + DIN + DSTATE + n] * eAl_s[l];
        split_store(sm, sm + 32768, SWZ256(l*256 + n*2), v);
    }
    const size_t pbase = ((size_t)(bc*NH) + h) * HD * DSTATE;
    for (int i = tid; i < 8192; i += 256) {
        int p = i >> 7, n = i & 127;
        float v = g_prev[pbase + i];
        split_store(sm + 65536, sm + 81920, SWZ256(p*256 + n*2), v);
    }
    __syncthreads();

    const int lane = tid & 31;
    const int wid = tid >> 5;
    const int wm = wid >> 1;      // 0..3  (m = l tile)
    const int wn = wid & 1;       // 0..1  (n = p tile)
    const uint32_t base = smem_u32(sm);
    float acc[2][4][4] = {};
    y_mma_block(acc, base, lane, wm, wn);
    __syncthreads();

    // ---- pass 2 tiles: A = W [l][s], B = xT [p][s]
    for (int i = tid; i < 16384; i += 256) {
        int l = i >> 7, s = i & 127;
        float v = 0.f;
        if (s <= l)
            v = g_cb[(size_t)bc*CHUNKQ*CHUNKQ + i] * __expf(acum_s[l] - acum_s[s]) * dt_s[s];
        split_store(sm, sm + 32768, SWZ256(l*256 + s*2), v);
    }
    for (int i = tid; i < 8192; i += 256) {
        int l = i >> 6, p = i & 63;
        float v = g_xbc[(size_t)(row0+l)*DXBC + h*HD + p];
        split_store(sm + 65536, sm + 81920, SWZ256(p*256 + l*2), v);
    }
    __syncthreads();
    y_mma_block(acc, base, lane, wm, wn);

    // ---- epilogue: + D*x, write Y
    const float dval = Dv[h];
    const int mr = lane >> 2;
    const int nb = (lane & 3)*2;
    #pragma unroll
    for (int mf = 0; mf < 2; ++mf) {
        #pragma unroll
        for (int nf = 0; nf < 4; ++nf) {
            int p = wn*32 + nf*8 + nb;
            #pragma unroll
            for (int rr = 0; rr < 2; ++rr) {
                int l = wm*32 + mf*16 + mr + rr*8;
                uint32_t o0 = SWZ256(p*256 + l*2);
                uint32_t o1 = SWZ256((p+1)*256 + l*2);
                float x0 = __bfloat162float(*(__nv_bfloat16*)(sm + 65536 + o0))
                         + __bfloat162float(*(__nv_bfloat16*)(sm + 81920 + o0));
                float x1 = __bfloat162float(*(__nv_bfloat16*)(sm + 65536 + o1))
                         + __bfloat162float(*(__nv_bfloat16*)(sm + 81920 + o1));
                float2 v = make_float2(acc[mf][nf][rr*2+0] + dval*x0,
                                       acc[mf][nf][rr*2+1] + dval*x1);
                *(float2*)&g_y[(size_t)(row0+l)*DIN + h*HD + p] = v;
            }
        }
    }
}

// ---------------- gating + RMSNorm ----------------
__global__ void norm_kernel(const float* __restrict__ norm_w)
{
    __shared__ float tbuf[DIN];
    __shared__ float red[256];
    int row = blockIdx.x;
    int tid = threadIdx.x;
    float partial = 0.f;
    for (int i = tid; i < DIN; i += 256) {
        float yv = g_y[(size_t)row*DIN + i];
        float zv = g_zx[(size_t)row*DPROJ + i];
        float t  = yv * (zv / (1.f + __expf(-zv)));
        tbuf[i] = t;
        partial += t*t;
    }
    red[tid] = partial;
    __syncthreads();
    for (int s = 128; s > 0; s >>= 1) {
        if (tid < s) red[tid] += red[tid + s];
        __syncthreads();
    }
    float scale = rsqrtf(red[0] / (float)DIN + 1e-5f);
    for (int i = tid; i < DIN; i += 256)
        g_y[(size_t)row*DIN + i] = tbuf[i] * scale * norm_w[i];
}

// ---------------- launch ----------------
extern "C" void kernel_launch(void* const* d_in, const int* in_sizes, int n_in,
                              void* d_out, int out_size)
{
    const float* feature = (const float*)d_in[0];
    const float* gate1   = (const float*)d_in[1];
    const float* in_w    = (const float*)d_in[2];
    const float* conv_w  = (const float*)d_in[3];
    const float* conv_b  = (const float*)d_in[4];
    const float* dt_bias = (const float*)d_in[5];
    const float* A_log   = (const float*)d_in[6];
    const float* Dv      = (const float*)d_in[7];
    const float* norm_w  = (const float*)d_in[8];
    const float* out_w   = (const float*)d_in[9];
    float* out = (float*)d_out;

    void* p_zx; cudaGetSymbolAddress(&p_zx, g_zx);
    void* p_y;  cudaGetSymbolAddress(&p_y,  g_y);
    void* p_a2; cudaGetSymbolAddress(&p_a2, g_a2);
    void* p_b2; cudaGetSymbolAddress(&p_b2, g_b2);
    __nv_bfloat16* a2 = (__nv_bfloat16*)p_a2;
    __nv_bfloat16* b2 = (__nv_bfloat16*)p_b2;

    cudaFuncSetAttribute(cb_kernel,  cudaFuncAttributeMaxDynamicSharedMemorySize, CB_SMEM_BYTES);
    cudaFuncSetAttribute(states_mma, cudaFuncAttributeMaxDynamicSharedMemorySize, STM_SMEM_BYTES);
    cudaFuncSetAttribute(y_mma,      cudaFuncAttributeMaxDynamicSharedMemorySize, YM_SMEM_BYTES);
    cudaFuncSetAttribute(gemm_mma,   cudaFuncAttributeMaxDynamicSharedMemorySize, GEMM_SMEM_BYTES);

    // 1. split conversion + GEMM1 (tensor cores)
    split_a_kernel<<<(NROWS*DMODEL + 255)/256, 256>>>(feature, a2, NROWS, DMODEL);
    split_b_kernel<<<(NPAD1*DMODEL + 255)/256, 256>>>(in_w, b2, DPROJ, NPAD1, DMODEL);
    gemm_mma<<<dim3(NPAD1/128, NROWS/128), 256, GEMM_SMEM_BYTES>>>(
        a2, b2, (float*)p_zx, KP1, DPROJ, DPROJ, nullptr, nullptr, 0);
    // 2. conv + silu
    conv_silu_kernel<<<(NROWS*DXBC + 255)/256, 256>>>(conv_w, conv_b);
    // 3. dt, per-chunk cumsum
    dt_kernel<<<(NROWS*NH + 255)/256, 256>>>(dt_bias);
    acum_kernel<<<NBC*NH, CHUNKQ>>>(A_log);
    // 4. CB per chunk (fp32)
    cb_kernel<<<NBC, 256, CB_SMEM_BYTES>>>();
    // 5. chunk states (tensor cores, split bf16)
    states_mma<<<NBC*NH, 128, STM_SMEM_BYTES>>>();
    // 6. inter-chunk recurrence (fully parallel lanes)
    scan_kernel<<<(BSZ*NH*HD*DSTATE)/512, 512>>>();
    // 7. Y (tensor cores, split bf16)
    y_mma<<<NBC*NH, 256, YM_SMEM_BYTES>>>(Dv);
    // 8. gating + RMSNorm
    norm_kernel<<<NROWS, 256>>>(norm_w);
    // 9. split conversion + GEMM2 (tensor cores) + residual epilogue
    split_a_kernel<<<(NROWS*DIN + 255)/256, 256>>>((const float*)p_y, a2, NROWS, DIN);
    split_b_kernel<<<(DMODEL*DIN + 255)/256, 256>>>(out_w, b2, DMODEL, DMODEL, DIN);
    gemm_mma<<<dim3(DMODEL/128, NROWS/128), 256, GEMM_SMEM_BYTES>>>(
        a2, b2, out, KP2, DMODEL, DMODEL, feature, gate1, 1);
}